// round 15
// baseline (speedup 1.0000x reference)
#include <cuda_runtime.h>
#include <cuda_fp16.h>
#include <cstdint>

#define MM 4096
#define KK 4096
#define NN 12288
#define GG 32            // K / 128 groups
#define NCHUNK 64        // K / 64

#define BM 128
#define BN 256

// ---- dynamic smem layout (tcgen05 path): B fp16 tiles + packed words ----
#define B16_OFF  0                       // 3 x 32768 (fp16 B tiles, SW128)
#define BPK_OFF  (3*32768)               // 3 x 8192  (packed B words)
#define CTRL_OFF (BPK_OFF + 3*8192)      // tmem ptr + 3 mbarriers
#define SMEM_BYTES (CTRL_OFF + 64)

// TMEM columns: D accum at 0..255, A buffers at 256 + b*32 (32 cols each)
#define TM_A_COL 256

#define SWZ(x) ((x) ^ (((x) >> 3) & 0x70))
#define IDESC ((1u << 4) | ((BN / 8) << 17) | ((BM / 16) << 24))  // f32 acc, f16 in

// SW128 K-major smem descriptor (LBO=1, SBO=64, version=1, layout=2)
#define DESC_BASE ((uint64_t(2) << 61) | (uint64_t(1) << 46) | \
                   (uint64_t(64) << 32) | (uint64_t(1) << 16))
#define MAKE_DESC(a) (DESC_BASE | ((uint64_t)((a) >> 4) & 0x3FFF))

// nibble interleave: position p within each 8-k group reads nibble ilv(p)
__host__ __device__ __forceinline__ int ilvf(int p) {
    return ((p >> 1) | ((p & 1) << 2));
}

// Scratch
__device__ __half g_A[(size_t)MM * KK];   // permuted+interleaved activations [M, K]
__device__ float  g_S[(size_t)GG * NN];   // group scales (g, n)
__device__ int    g_perm[KK];
__device__ int    g_f32;                  // 1 if fp16 tensors arrive upcast to fp32

// ---------------------------------------------------------------------------
// Fused prep: dtype probe + inverse-perm scatter + scale table. One launch.
__global__ void prep(const int* __restrict__ invperm, const int* __restrict__ qs,
                     const void* __restrict__ qsm) {
    int idx = blockIdx.x * blockDim.x + threadIdx.x;   // GG*NN threads
    const float* f = (const float*)qsm;
    int ok = 1;
#pragma unroll
    for (int i = 0; i < 16; ++i) {
        float v = f[i];
        if (!(v > 1e-8f && v < 0.004f)) ok = 0;
    }
    if (idx == 0) g_f32 = ok;
    if (idx < KK) g_perm[invperm[idx]] = idx;
    int n = idx % NN, g = idx / NN;
    float smax = ok ? f[g] : __half2float(((const __half*)qsm)[g]);
    int sq = qs[g * (NN / 8) + (n >> 3)];
    int sc = (sq >> ((n & 7) * 4)) & 0xF;
    g_S[idx] = (float)((sc + 1) * (sc + 1)) * smax;
}

// g_A[m, k'] = x[m, perm[(k' & ~7) | ilv(k' & 7)]]  (4 elems/thread, vector store)
__global__ void permute_act(const void* __restrict__ inp) {
    int t = blockIdx.x * blockDim.x + threadIdx.x;   // MM*KK/4 threads
    int base = t * 4;
    int m = base >> 12;
    int k0 = base & (KK - 1);
    const int mrow = m << 12;
    int src[4];
#pragma unroll
    for (int j = 0; j < 4; ++j) {
        int k = k0 + j;
        src[j] = g_perm[(k & ~7) | ilvf(k & 7)];
    }
    __half v[4];
    if (g_f32) {
        const float* x = (const float*)inp + mrow;
#pragma unroll
        for (int j = 0; j < 4; ++j) v[j] = __float2half(x[src[j]]);
    } else {
        const __half* x = (const __half*)inp + mrow;
#pragma unroll
        for (int j = 0; j < 4; ++j) v[j] = x[src[j]];
    }
    *(uint2*)(g_A + base) = *(uint2*)v;
}

// ---------------------------------------------------------------------------
__device__ __forceinline__ uint32_t elect_one() {
    uint32_t p;
    asm volatile("{.reg .pred p; elect.sync _|p, 0xFFFFFFFF; selp.b32 %0,1,0,p;}"
                 : "=r"(p));
    return p;
}
__device__ __forceinline__ void cp16(uint32_t dst, const void* src) {
    asm volatile("cp.async.cg.shared.global [%0], [%1], 16;\n" :: "r"(dst), "l"(src));
}
__device__ __forceinline__ void mbar_wait(uint32_t a, uint32_t par) {
    uint32_t done;
    asm volatile("{.reg .pred p; mbarrier.try_wait.parity.acquire.cta.shared::cta.b64 p, [%1], %2;"
                 " selp.b32 %0,1,0,p;}" : "=r"(done) : "r"(a), "r"(par) : "memory");
    if (!done) {
        asm volatile("{.reg .pred P1; WL_%=: mbarrier.try_wait.parity.acquire.cta.shared::cta.b64 P1, [%0], %1, 0x989680;"
                     " @P1 bra.uni WD_%=; bra.uni WL_%=; WD_%=:}"
                     :: "r"(a), "r"(par) : "memory");
    }
}

// ---------------------------------------------------------------------------
// One CTA = 128x256 output tile, 512 threads. TS-mode MMA (A in TMEM).
__global__ __launch_bounds__(512, 1) __cluster_dims__(1, 1, 1)
void gemm_tc(void* __restrict__ outv, const void* __restrict__ biasv,
             const int* __restrict__ qw) {
    extern __shared__ __align__(1024) char sm[];
    const int tid = threadIdx.x;
    const int bid = blockIdx.x;
    const int nb = bid % (NN / BN);
    const int mb = bid / (NN / BN);
    const int n0 = nb * BN;
    const int m0 = mb * BM;
    const int f32m = g_f32;

#ifdef __CUDA_ARCH_FEAT_SM103_ALL
    // ===================== tcgen05 fused-dequant TS path =====================
    const uint32_t smb = (uint32_t)__cvta_generic_to_shared(sm);
    if (tid < 32) {
        asm volatile("tcgen05.alloc.cta_group::1.sync.aligned.shared::cta.b32 [%0], %1;"
                     :: "r"(smb + CTRL_OFF), "r"(512u) : "memory");
        asm volatile("tcgen05.relinquish_alloc_permit.cta_group::1.sync.aligned;");
    }
    if (tid == 0) {
#pragma unroll
        for (int s = 0; s < 3; ++s)
            asm volatile("mbarrier.init.shared.b64 [%0], %1;"
                         :: "r"(smb + CTRL_OFF + 8 + s * 8), "r"(1u) : "memory");
    }
    __syncthreads();
    uint32_t tmem;
    asm volatile("ld.shared.b32 %0, [%1];" : "=r"(tmem) : "r"(smb + CTRL_OFF));

    const __half* Ag = g_A + (size_t)m0 * KK;
    const int*    Qg = qw + n0;

    // packed-words chunk loader (8 KB)
    auto ldpk = [&](int k) {
        int b = k % 3;
        uint32_t Pb = smb + BPK_OFF + b * 8192;
        int r = tid >> 6, c4 = (tid & 63) * 4;
        const void* src = Qg + (size_t)(k * 8 + r) * NN + c4;
        cp16(Pb + tid * 16, src);
    };

    // A-producer state (warps 0-3): each thread owns one M row
    uint32_t arA[32];
    const int arow = tid;                      // valid when tid < 128
    auto ldA = [&](int k) {
        const uint4* src = (const uint4*)(Ag + (size_t)arow * KK + k * 64);
#pragma unroll
        for (int i = 0; i < 8; ++i) *(uint4*)(arA + i * 4) = src[i];
    };
    const uint32_t a_woff = ((uint32_t)(tid >> 5)) << 21;

    ldpk(0);
    asm volatile("cp.async.commit_group;" ::: "memory");
    ldpk(1);
    asm volatile("cp.async.commit_group;" ::: "memory");
    if (tid < 128) ldA(0);

    const __half2 k1032 = __half2half2(__ushort_as_half((unsigned short)0x6408));
    const int dq_n = tid & 255;
    const int dq_r0 = (tid >> 8) * 4;

    for (int k = 0; k < NCHUNK; ++k) {
        const int b = k % 3;

        // ---- A(k): regs -> TMEM buf b; prefetch A(k+1) ----
        if (tid < 128) {
            uint32_t ta = tmem + TM_A_COL + b * 32 + a_woff;
            asm volatile(
                "tcgen05.st.sync.aligned.32x32b.x32.b32 [%0], "
                "{%1,%2,%3,%4,%5,%6,%7,%8,%9,%10,%11,%12,%13,%14,%15,%16,"
                "%17,%18,%19,%20,%21,%22,%23,%24,%25,%26,%27,%28,%29,%30,%31,%32};"
                :: "r"(ta),
                   "r"(arA[0]),  "r"(arA[1]),  "r"(arA[2]),  "r"(arA[3]),
                   "r"(arA[4]),  "r"(arA[5]),  "r"(arA[6]),  "r"(arA[7]),
                   "r"(arA[8]),  "r"(arA[9]),  "r"(arA[10]), "r"(arA[11]),
                   "r"(arA[12]), "r"(arA[13]), "r"(arA[14]), "r"(arA[15]),
                   "r"(arA[16]), "r"(arA[17]), "r"(arA[18]), "r"(arA[19]),
                   "r"(arA[20]), "r"(arA[21]), "r"(arA[22]), "r"(arA[23]),
                   "r"(arA[24]), "r"(arA[25]), "r"(arA[26]), "r"(arA[27]),
                   "r"(arA[28]), "r"(arA[29]), "r"(arA[30]), "r"(arA[31])
                : "memory");
            asm volatile("tcgen05.wait::st.sync.aligned;" ::: "memory");
            if (k + 1 < NCHUNK) ldA(k + 1);
        }

        if (k == NCHUNK - 1) asm volatile("cp.async.wait_group 0;" ::: "memory");
        else                 asm volatile("cp.async.wait_group 1;" ::: "memory");
        __syncthreads();

        {   // dequant packed buf b -> fp16 B tile [n][k], SW128 (interleaved k)
            int g = k >> 1;
            float s = __ldg(g_S + (size_t)g * NN + n0 + dq_n);
            __half2 s2 = __half2half2(__float2half_rn(s));
            const int* qp = (const int*)(sm + BPK_OFF + b * 8192);
            char* bb = sm + B16_OFF + b * 32768;
#pragma unroll
            for (int rr = 0; rr < 4; ++rr) {
                int r = dq_r0 + rr;
                int w = qp[r * 256 + dq_n];
                uint32_t t0 = ((uint32_t)(w)       & 0x000F000Fu) | 0x64006400u;
                uint32_t t1 = ((uint32_t)(w >> 4)  & 0x000F000Fu) | 0x64006400u;
                uint32_t t2 = ((uint32_t)(w >> 8)  & 0x000F000Fu) | 0x64006400u;
                uint32_t t3 = ((uint32_t)(w >> 12) & 0x000F000Fu) | 0x64006400u;
                __half2 h0 = __hmul2(__hsub2(*(__half2*)&t0, k1032), s2);
                __half2 h1 = __hmul2(__hsub2(*(__half2*)&t1, k1032), s2);
                __half2 h2 = __hmul2(__hsub2(*(__half2*)&t2, k1032), s2);
                __half2 h3 = __hmul2(__hsub2(*(__half2*)&t3, k1032), s2);
                uint32_t off = SWZ((uint32_t)(dq_n * 128 + r * 16));
                *(uint4*)(bb + off) = make_uint4(*(uint32_t*)&h0, *(uint32_t*)&h1,
                                                 *(uint32_t*)&h2, *(uint32_t*)&h3);
            }
        }
        asm volatile("tcgen05.fence::before_thread_sync;" ::: "memory");
        __syncthreads();

        if (tid < 32) {
            asm volatile("tcgen05.fence::after_thread_sync;" ::: "memory");
            if (elect_one()) {
                uint32_t at = tmem + TM_A_COL + b * 32;
                uint64_t bd = MAKE_DESC(smb + B16_OFF + b * 32768);
#pragma unroll
                for (int ks = 0; ks < 4; ++ks) {
                    uint32_t en = (k | ks) != 0;
                    asm volatile("{\n\t.reg .pred p;\n\tsetp.ne.u32 p, %4, 0;\n\t"
                                 "tcgen05.mma.cta_group::1.kind::f16 [%0], [%1], %2, %3, {%5,%5,%5,%5}, p;\n\t}"
                                 :: "r"(tmem), "r"(at + ks * 8), "l"(bd + 2 * ks),
                                    "r"(IDESC), "r"(en), "r"(0u) : "memory");
                }
                asm volatile("tcgen05.commit.cta_group::1.mbarrier::arrive::one.shared::cluster.b64 [%0];"
                             :: "r"(smb + CTRL_OFF + 8 + b * 8) : "memory");
            }
        }

        if (k >= 1) mbar_wait(smb + CTRL_OFF + 8 + ((k - 1) % 3) * 8, ((k - 1) / 3) & 1);
        if (k + 2 < NCHUNK) {
            ldpk(k + 2);
            asm volatile("cp.async.commit_group;" ::: "memory");
        }
    }

    mbar_wait(smb + CTRL_OFF + 8 + ((NCHUNK - 1) % 3) * 8, ((NCHUNK - 1) / 3) & 1);
    asm volatile("tcgen05.fence::after_thread_sync;" ::: "memory");

    // epilogue: 16 warps; warp w -> subpartition (w&3), col group (w>>2)*64
    const int w = tid >> 5, lane = tid & 31;
    const int sub = w & 3;
    const int colbase = (w >> 2) * 64;
    const int m = m0 + sub * 32 + lane;

#pragma unroll
    for (int cc = 0; cc < 2; ++cc) {
        uint32_t d[32];
        asm volatile(
            "tcgen05.ld.sync.aligned.32x32b.x32.b32 "
            "{%0,%1,%2,%3,%4,%5,%6,%7,%8,%9,%10,%11,%12,%13,%14,%15,"
            "%16,%17,%18,%19,%20,%21,%22,%23,%24,%25,%26,%27,%28,%29,%30,%31}, [%32];"
            : "=r"(d[0]), "=r"(d[1]), "=r"(d[2]), "=r"(d[3]), "=r"(d[4]), "=r"(d[5]),
              "=r"(d[6]), "=r"(d[7]), "=r"(d[8]), "=r"(d[9]), "=r"(d[10]), "=r"(d[11]),
              "=r"(d[12]), "=r"(d[13]), "=r"(d[14]), "=r"(d[15]), "=r"(d[16]), "=r"(d[17]),
              "=r"(d[18]), "=r"(d[19]), "=r"(d[20]), "=r"(d[21]), "=r"(d[22]), "=r"(d[23]),
              "=r"(d[24]), "=r"(d[25]), "=r"(d[26]), "=r"(d[27]), "=r"(d[28]), "=r"(d[29]),
              "=r"(d[30]), "=r"(d[31])
            : "r"(tmem + colbase + cc * 32));
        asm volatile("tcgen05.wait::ld.sync.aligned;" ::: "memory");

        int colstart = n0 + colbase + cc * 32;
        if (!f32m) {
            const __half2* bp = (const __half2*)biasv + (colstart >> 1);
            uint4 v[4];
            __half2* hv = (__half2*)v;
#pragma unroll
            for (int j = 0; j < 16; ++j) {
                float2 bf = __half22float2(bp[j]);
                hv[j] = __floats2half2_rn(__uint_as_float(d[2 * j]) + bf.x,
                                          __uint_as_float(d[2 * j + 1]) + bf.y);
            }
            uint4* dst = (uint4*)((__half*)outv + (size_t)m * NN + colstart);
            dst[0] = v[0]; dst[1] = v[1]; dst[2] = v[2]; dst[3] = v[3];
        } else {
            const float2* bp = (const float2*)biasv + (colstart >> 1);
            float2* dst = (float2*)((float*)outv + (size_t)m * NN + colstart);
#pragma unroll
            for (int j = 0; j < 16; ++j) {
                float2 bf = bp[j];
                dst[j] = make_float2(__uint_as_float(d[2 * j]) + bf.x,
                                     __uint_as_float(d[2 * j + 1]) + bf.y);
            }
        }
    }
    asm volatile("tcgen05.fence::before_thread_sync;" ::: "memory");
    __syncthreads();
    if (tid == 0) {
#pragma unroll
        for (int s = 0; s < 3; ++s)
            asm volatile("mbarrier.inval.shared.b64 [%0];"
                         :: "r"(smb + CTRL_OFF + 8 + s * 8) : "memory");
    }
    __syncthreads();
    if (tid < 32)
        asm volatile("tcgen05.dealloc.cta_group::1.sync.aligned.b32 %0, %1;"
                     :: "r"(tmem), "r"(512u));

#else
    // ============ compile-pass fallback (never runs on sm_103a) ============
    for (int e = tid; e < BM * BN; e += 512) {
        int mr = m0 + (e >> 8);
        int n  = n0 + (e & 255);
        float acc;
        if (f32m) acc = ((const float*)biasv)[n];
        else      acc = __half2float(((const __half*)biasv)[n]);
        const __half* Arow = g_A + (size_t)mr * KK;
        for (int kp = 0; kp < KK; kp += 8) {
            int word = qw[(size_t)(kp >> 3) * NN + n];
            float s = g_S[(size_t)(kp >> 7) * NN + n];
#pragma unroll
            for (int p = 0; p < 8; ++p) {
                int nib = (word >> (ilvf(p) * 4)) & 0xF;
                acc += __half2float(Arow[kp + p]) * (float)(nib - 8) * s;
            }
        }
        if (f32m) ((float*)outv)[(size_t)mr * NN + n] = acc;
        else      ((__half*)outv)[(size_t)mr * NN + n] = __float2half(acc);
    }
#endif
}

// ---------------------------------------------------------------------------
extern "C" void kernel_launch(void* const* d_in, const int* in_sizes, int n_in,
                              void* d_out, int out_size) {
    const void* input   = d_in[0];              // [M, K] fp16 (or fp32-upcast)
    const int*  qw      = (const int*)d_in[1];  // [K/8, N] int32
    const int*  qs      = (const int*)d_in[2];  // [G, N/8] int32
    const void* qsm     = d_in[3];              // [G] fp16 (or fp32-upcast)
    const int*  invperm = (const int*)d_in[4];  // [K] int32
    const void* bias    = d_in[5];              // [N] fp16 (or fp32-upcast)

    prep<<<(GG * NN) / 256, 256>>>(invperm, qs, qsm);
    permute_act<<<(MM * KK / 4) / 256, 256>>>(input);

    cudaFuncSetAttribute(gemm_tc, cudaFuncAttributeMaxDynamicSharedMemorySize,
                         SMEM_BYTES);
    gemm_tc<<<(MM / BM) * (NN / BN), 512, SMEM_BYTES>>>(d_out, bias, qw);
}

// round 17
// speedup vs baseline: 1.1311x; 1.1311x over previous
#include <cuda_runtime.h>
#include <cuda_fp16.h>
#include <cstdint>

#define MM 4096
#define KK 4096
#define NN 12288
#define GG 32            // K / 128 groups
#define NCHUNK 64        // K / 64

#define BM 128
#define BN 256

// ---- dynamic smem layout: 3-stage B fp16 + A fp16 tiles ----
#define B16_OFF  0                       // 3 x 32768 (fp16 B tiles, SW128)
#define A_OFF    (3*32768)               // 3 x 16384 (fp16 A tiles, SW128)
#define CTRL_OFF (A_OFF + 3*16384)       // tmem ptr + 3 mbarriers
#define SMEM_BYTES (CTRL_OFF + 64)

#define SWZ(x) ((x) ^ (((x) >> 3) & 0x70))
#define IDESC ((1u << 4) | ((BN / 8) << 17) | ((BM / 16) << 24))  // f32 acc, f16 in

// SW128 K-major smem descriptor (LBO=1, SBO=64, version=1, layout=2)
#define DESC_BASE ((uint64_t(2) << 61) | (uint64_t(1) << 46) | \
                   (uint64_t(64) << 32) | (uint64_t(1) << 16))
#define MAKE_DESC(a) (DESC_BASE | ((uint64_t)((a) >> 4) & 0x3FFF))

// nibble interleave: position p within each 8-k group reads nibble ilv(p)
__host__ __device__ __forceinline__ int ilvf(int p) {
    return ((p >> 1) | ((p & 1) << 2));
}

// Scratch
__device__ __half g_A[(size_t)MM * KK];   // permuted+interleaved activations [M, K]
__device__ float  g_S[(size_t)GG * NN];   // group scales (g, n)
__device__ int    g_perm[KK];
__device__ int    g_f32;                  // 1 if fp16 tensors arrive upcast to fp32

// ---------------------------------------------------------------------------
// Fused prep: dtype probe + inverse-perm scatter + scale table. One launch.
__global__ void prep(const int* __restrict__ invperm, const int* __restrict__ qs,
                     const void* __restrict__ qsm) {
    int idx = blockIdx.x * blockDim.x + threadIdx.x;   // GG*NN threads
    const float* f = (const float*)qsm;
    int ok = 1;
#pragma unroll
    for (int i = 0; i < 16; ++i) {
        float v = f[i];
        if (!(v > 1e-8f && v < 0.004f)) ok = 0;
    }
    if (idx == 0) g_f32 = ok;
    if (idx < KK) g_perm[invperm[idx]] = idx;
    int n = idx % NN, g = idx / NN;
    float smax = ok ? f[g] : __half2float(((const __half*)qsm)[g]);
    int sq = qs[g * (NN / 8) + (n >> 3)];
    int sc = (sq >> ((n & 7) * 4)) & 0xF;
    g_S[idx] = (float)((sc + 1) * (sc + 1)) * smax;
}

// g_A[m, k'] = x[m, perm[(k' & ~7) | ilv(k' & 7)]]  (4 elems/thread, vector store)
__global__ void permute_act(const void* __restrict__ inp) {
    int t = blockIdx.x * blockDim.x + threadIdx.x;   // MM*KK/4 threads
    int base = t * 4;
    int m = base >> 12;
    int k0 = base & (KK - 1);
    const int mrow = m << 12;
    int src[4];
#pragma unroll
    for (int j = 0; j < 4; ++j) {
        int k = k0 + j;
        src[j] = g_perm[(k & ~7) | ilvf(k & 7)];
    }
    __half v[4];
    if (g_f32) {
        const float* x = (const float*)inp + mrow;
#pragma unroll
        for (int j = 0; j < 4; ++j) v[j] = __float2half(x[src[j]]);
    } else {
        const __half* x = (const __half*)inp + mrow;
#pragma unroll
        for (int j = 0; j < 4; ++j) v[j] = x[src[j]];
    }
    *(uint2*)(g_A + base) = *(uint2*)v;
}

// ---------------------------------------------------------------------------
__device__ __forceinline__ uint32_t elect_one() {
    uint32_t p;
    asm volatile("{.reg .pred p; elect.sync _|p, 0xFFFFFFFF; selp.b32 %0,1,0,p;}"
                 : "=r"(p));
    return p;
}
__device__ __forceinline__ void cp16(uint32_t dst, const void* src) {
    asm volatile("cp.async.cg.shared.global [%0], [%1], 16;\n" :: "r"(dst), "l"(src));
}
__device__ __forceinline__ void mbar_wait(uint32_t a, uint32_t par) {
    uint32_t done;
    asm volatile("{.reg .pred p; mbarrier.try_wait.parity.acquire.cta.shared::cta.b64 p, [%1], %2;"
                 " selp.b32 %0,1,0,p;}" : "=r"(done) : "r"(a), "r"(par) : "memory");
    if (!done) {
        asm volatile("{.reg .pred P1; WL_%=: mbarrier.try_wait.parity.acquire.cta.shared::cta.b64 P1, [%0], %1, 0x989680;"
                     " @P1 bra.uni WD_%=; bra.uni WL_%=; WD_%=:}"
                     :: "r"(a), "r"(par) : "memory");
    }
}

// ---------------------------------------------------------------------------
// One CTA = 128x256 output tile, 512 threads. SS-mode MMA, packed W via LDG.
__global__ __launch_bounds__(512, 1) __cluster_dims__(1, 1, 1)
void gemm_tc(void* __restrict__ outv, const void* __restrict__ biasv,
             const int* __restrict__ qw) {
    extern __shared__ __align__(1024) char sm[];
    const int tid = threadIdx.x;
    const int bid = blockIdx.x;
    const int nb = bid % (NN / BN);
    const int mb = bid / (NN / BN);
    const int n0 = nb * BN;
    const int m0 = mb * BM;
    const int f32m = g_f32;

#ifdef __CUDA_ARCH_FEAT_SM103_ALL
    // ===================== tcgen05 fused-dequant SS path =====================
    const uint32_t smb = (uint32_t)__cvta_generic_to_shared(sm);
    if (tid < 32) {
        asm volatile("tcgen05.alloc.cta_group::1.sync.aligned.shared::cta.b32 [%0], %1;"
                     :: "r"(smb + CTRL_OFF), "r"(256u) : "memory");
        asm volatile("tcgen05.relinquish_alloc_permit.cta_group::1.sync.aligned;");
    }
    if (tid == 0) {
#pragma unroll
        for (int s = 0; s < 3; ++s)
            asm volatile("mbarrier.init.shared.b64 [%0], %1;"
                         :: "r"(smb + CTRL_OFF + 8 + s * 8), "r"(1u) : "memory");
    }
    __syncthreads();
    uint32_t tmem;
    asm volatile("ld.shared.b32 %0, [%1];" : "=r"(tmem) : "r"(smb + CTRL_OFF));

    const __half* Ag = g_A + (size_t)m0 * KK;

    // A-tile loader (16 KB, 2 x cp16 per thread)
    auto ldA = [&](int k) {
        int b = k % 3;
        uint32_t Ab = smb + A_OFF + b * 16384;
#pragma unroll
        for (int i = 0; i < 2; ++i) {
            int idx = tid + i * 512;            // 0..1023
            int row = idx >> 3, c16 = idx & 7;
            const void* src = Ag + (size_t)row * KK + k * 64 + c16 * 8;
            uint32_t off = (uint32_t)(row * 128 + c16 * 16);
            cp16(Ab + SWZ(off), src);
        }
    };

    // packed-word register prefetch: 4 words (rows dq_r0..+3, col dq_n)
    const int dq_n = tid & 255;
    const int dq_r0 = (tid >> 8) * 4;
    const int* Qt = qw + n0 + dq_n;             // thread's packed column
    const float* St = g_S + n0 + dq_n;          // thread's scale column
    uint32_t pk[2][4];
    float    sf[2];
    auto ldpk = [&](int k) {
        const int* p = Qt + (size_t)(k * 8 + dq_r0) * NN;
        int s = k & 1;
#pragma unroll
        for (int rr = 0; rr < 4; ++rr) pk[s][rr] = __ldg((const uint32_t*)p + (size_t)rr * NN);
        sf[s] = __ldg(St + (size_t)(k >> 1) * NN);
    };

    ldA(0);
    asm volatile("cp.async.commit_group;" ::: "memory");
    ldA(1);
    asm volatile("cp.async.commit_group;" ::: "memory");
    ldpk(0);
    ldpk(1);

    const __half2 k1032 = __half2half2(__ushort_as_half((unsigned short)0x6408));

    for (int k = 0; k < NCHUNK; ++k) {
        const int b = k % 3;
        if (k == NCHUNK - 1) asm volatile("cp.async.wait_group 0;" ::: "memory");
        else                 asm volatile("cp.async.wait_group 1;" ::: "memory");

        {   // dequant regs -> fp16 B tile [n][k], SW128 (interleaved k order)
            const int s = k & 1;
            __half2 s2 = __half2half2(__float2half_rn(sf[s]));
            char* bb = sm + B16_OFF + b * 32768;
#pragma unroll
            for (int rr = 0; rr < 4; ++rr) {
                uint32_t w = pk[s][rr];
                uint32_t t0 = (w         & 0x000F000Fu) | 0x64006400u;
                uint32_t t1 = ((w >> 4)  & 0x000F000Fu) | 0x64006400u;
                uint32_t t2 = ((w >> 8)  & 0x000F000Fu) | 0x64006400u;
                uint32_t t3 = ((w >> 12) & 0x000F000Fu) | 0x64006400u;
                __half2 h0 = __hmul2(__hsub2(*(__half2*)&t0, k1032), s2);
                __half2 h1 = __hmul2(__hsub2(*(__half2*)&t1, k1032), s2);
                __half2 h2 = __hmul2(__hsub2(*(__half2*)&t2, k1032), s2);
                __half2 h3 = __hmul2(__hsub2(*(__half2*)&t3, k1032), s2);
                uint32_t off = SWZ((uint32_t)(dq_n * 128 + (dq_r0 + rr) * 16));
                *(uint4*)(bb + off) = make_uint4(*(uint32_t*)&h0, *(uint32_t*)&h1,
                                                 *(uint32_t*)&h2, *(uint32_t*)&h3);
            }
        }
        // prefetch packed words + scale for chunk k+2 (overlaps MMA k)
        if (k + 2 < NCHUNK) ldpk(k + 2);

        asm volatile("tcgen05.fence::before_thread_sync;" ::: "memory");
        __syncthreads();

        if (tid < 32) {
            asm volatile("tcgen05.fence::after_thread_sync;" ::: "memory");
            if (elect_one()) {
                uint64_t ad = MAKE_DESC(smb + A_OFF + b * 16384);
                uint64_t bd = MAKE_DESC(smb + B16_OFF + b * 32768);
#pragma unroll
                for (int ks = 0; ks < 4; ++ks) {
                    uint32_t en = (k | ks) != 0;
                    asm volatile("{\n\t.reg .pred p;\n\tsetp.ne.u32 p, %4, 0;\n\t"
                                 "tcgen05.mma.cta_group::1.kind::f16 [%0], %1, %2, %3, {%5,%5,%5,%5}, p;\n\t}"
                                 :: "r"(tmem), "l"(ad + 2 * ks), "l"(bd + 2 * ks),
                                    "r"(IDESC), "r"(en), "r"(0u) : "memory");
                }
                asm volatile("tcgen05.commit.cta_group::1.mbarrier::arrive::one.shared::cluster.b64 [%0];"
                             :: "r"(smb + CTRL_OFF + 8 + b * 8) : "memory");
            }
        }

        if (k >= 1) mbar_wait(smb + CTRL_OFF + 8 + ((k - 1) % 3) * 8, ((k - 1) / 3) & 1);
        if (k + 2 < NCHUNK) {
            ldA(k + 2);
            asm volatile("cp.async.commit_group;" ::: "memory");
        }
    }

    mbar_wait(smb + CTRL_OFF + 8 + ((NCHUNK - 1) % 3) * 8, ((NCHUNK - 1) / 3) & 1);
    asm volatile("tcgen05.fence::after_thread_sync;" ::: "memory");

    // epilogue: 16 warps; warp w -> subpartition (w&3), col group (w>>2)*64
    const int w = tid >> 5, lane = tid & 31;
    const int sub = w & 3;
    const int colbase = (w >> 2) * 64;
    const int m = m0 + sub * 32 + lane;

#pragma unroll
    for (int cc = 0; cc < 2; ++cc) {
        uint32_t d[32];
        asm volatile(
            "tcgen05.ld.sync.aligned.32x32b.x32.b32 "
            "{%0,%1,%2,%3,%4,%5,%6,%7,%8,%9,%10,%11,%12,%13,%14,%15,"
            "%16,%17,%18,%19,%20,%21,%22,%23,%24,%25,%26,%27,%28,%29,%30,%31}, [%32];"
            : "=r"(d[0]), "=r"(d[1]), "=r"(d[2]), "=r"(d[3]), "=r"(d[4]), "=r"(d[5]),
              "=r"(d[6]), "=r"(d[7]), "=r"(d[8]), "=r"(d[9]), "=r"(d[10]), "=r"(d[11]),
              "=r"(d[12]), "=r"(d[13]), "=r"(d[14]), "=r"(d[15]), "=r"(d[16]), "=r"(d[17]),
              "=r"(d[18]), "=r"(d[19]), "=r"(d[20]), "=r"(d[21]), "=r"(d[22]), "=r"(d[23]),
              "=r"(d[24]), "=r"(d[25]), "=r"(d[26]), "=r"(d[27]), "=r"(d[28]), "=r"(d[29]),
              "=r"(d[30]), "=r"(d[31])
            : "r"(tmem + colbase + cc * 32));
        asm volatile("tcgen05.wait::ld.sync.aligned;" ::: "memory");

        int colstart = n0 + colbase + cc * 32;
        if (!f32m) {
            const __half2* bp = (const __half2*)biasv + (colstart >> 1);
            uint4 v[4];
            __half2* hv = (__half2*)v;
#pragma unroll
            for (int j = 0; j < 16; ++j) {
                float2 bf = __half22float2(bp[j]);
                hv[j] = __floats2half2_rn(__uint_as_float(d[2 * j]) + bf.x,
                                          __uint_as_float(d[2 * j + 1]) + bf.y);
            }
            uint4* dst = (uint4*)((__half*)outv + (size_t)m * NN + colstart);
            dst[0] = v[0]; dst[1] = v[1]; dst[2] = v[2]; dst[3] = v[3];
        } else {
            const float2* bp = (const float2*)biasv + (colstart >> 1);
            float2* dst = (float2*)((float*)outv + (size_t)m * NN + colstart);
#pragma unroll
            for (int j = 0; j < 16; ++j) {
                float2 bf = bp[j];
                dst[j] = make_float2(__uint_as_float(d[2 * j]) + bf.x,
                                     __uint_as_float(d[2 * j + 1]) + bf.y);
            }
        }
    }
    asm volatile("tcgen05.fence::before_thread_sync;" ::: "memory");
    __syncthreads();
    if (tid == 0) {
#pragma unroll
        for (int s = 0; s < 3; ++s)
            asm volatile("mbarrier.inval.shared.b64 [%0];"
                         :: "r"(smb + CTRL_OFF + 8 + s * 8) : "memory");
    }
    __syncthreads();
    if (tid < 32)
        asm volatile("tcgen05.dealloc.cta_group::1.sync.aligned.b32 %0, %1;"
                     :: "r"(tmem), "r"(256u));

#else
    // ============ compile-pass fallback (never runs on sm_103a) ============
    for (int e = tid; e < BM * BN; e += 512) {
        int mr = m0 + (e >> 8);
        int n  = n0 + (e & 255);
        float acc;
        if (f32m) acc = ((const float*)biasv)[n];
        else      acc = __half2float(((const __half*)biasv)[n]);
        const __half* Arow = g_A + (size_t)mr * KK;
        for (int kp = 0; kp < KK; kp += 8) {
            int word = qw[(size_t)(kp >> 3) * NN + n];
            float s = g_S[(size_t)(kp >> 7) * NN + n];
#pragma unroll
            for (int p = 0; p < 8; ++p) {
                int nib = (word >> (ilvf(p) * 4)) & 0xF;
                acc += __half2float(Arow[kp + p]) * (float)(nib - 8) * s;
            }
        }
        if (f32m) ((float*)outv)[(size_t)mr * NN + n] = acc;
        else      ((__half*)outv)[(size_t)mr * NN + n] = __float2half(acc);
    }
#endif
}

// ---------------------------------------------------------------------------
extern "C" void kernel_launch(void* const* d_in, const int* in_sizes, int n_in,
                              void* d_out, int out_size) {
    const void* input   = d_in[0];              // [M, K] fp16 (or fp32-upcast)
    const int*  qw      = (const int*)d_in[1];  // [K/8, N] int32
    const int*  qs      = (const int*)d_in[2];  // [G, N/8] int32
    const void* qsm     = d_in[3];              // [G] fp16 (or fp32-upcast)
    const int*  invperm = (const int*)d_in[4];  // [K] int32
    const void* bias    = d_in[5];              // [N] fp16 (or fp32-upcast)

    prep<<<(GG * NN) / 256, 256>>>(invperm, qs, qsm);
    permute_act<<<(MM * KK / 4) / 256, 256>>>(input);

    cudaFuncSetAttribute(gemm_tc, cudaFuncAttributeMaxDynamicSharedMemorySize,
                         SMEM_BYTES);
    gemm_tc<<<(MM / BM) * (NN / BN), 512, SMEM_BYTES>>>(d_out, bias, qw);
}